// round 3
// baseline (speedup 1.0000x reference)
#include <cuda_runtime.h>
#include <cstdint>
#include <cstddef>

#define NTN   32768
#define CCH   128
#define BATCH 64
#define NNODE 512
#define NH    4
#define DHEAD 32
#define NEDGE 524288
#define EPSBN 1e-5f

// ---------------- scratch (static device globals; no allocation) ----------------
__device__ int   d_cnt[NTN];
__device__ int   d_offs[NTN + 1];
__device__ int   d_cursor[NTN];
__device__ int   d_ebin[NEDGE];
__device__ float d_agg[NTN * CCH];
__device__ float d_h1[NTN * CCH];
__device__ float d_qkv[NTN * 3 * CCH];
__device__ float d_ao[NTN * CCH];
__device__ float d_h2[NTN * CCH];
__device__ float d_out1[NTN * CCH];
__device__ float d_hid[NTN * 2 * CCH];
__device__ float d_out2[NTN * CCH];
__device__ float d_stats[6 * CCH];   // [sum1, sq1, sum2, sq2, sum3, sq3]

// ---------------- init: zero counters + stats ----------------
__global__ void k_init() {
    int i = blockIdx.x * blockDim.x + threadIdx.x;
    if (i < NTN) d_cnt[i] = 0;
    if (i < 6 * CCH) d_stats[i] = 0.f;
}

// ---------------- edge degree count ----------------
__global__ void k_count(const int* __restrict__ ei) {
    int e = blockIdx.x * blockDim.x + threadIdx.x;
    if (e < NEDGE) atomicAdd(&d_cnt[ei[NEDGE + e]], 1);
}

// ---------------- exclusive scan of degrees (single CTA, 1024 thr x 32) ----------------
__global__ void k_scan() {
    __shared__ int part[1024];
    int tid = threadIdx.x;
    int base = tid * 32;
    int local[32];
    int s = 0;
    #pragma unroll
    for (int i = 0; i < 32; i++) { local[i] = d_cnt[base + i]; s += local[i]; }
    part[tid] = s;
    __syncthreads();
    for (int off = 1; off < 1024; off <<= 1) {
        int v = (tid >= off) ? part[tid - off] : 0;
        __syncthreads();
        part[tid] += v;
        __syncthreads();
    }
    int run = (tid == 0) ? 0 : part[tid - 1];
    #pragma unroll
    for (int i = 0; i < 32; i++) {
        d_offs[base + i] = run;
        d_cursor[base + i] = run;
        run += local[i];
    }
    if (tid == 1023) d_offs[NTN] = run;
}

// ---------------- bin edges by dst ----------------
__global__ void k_bin(const int* __restrict__ ei) {
    int e = blockIdx.x * blockDim.x + threadIdx.x;
    if (e < NEDGE) {
        int src = ei[e];
        int dst = ei[NEDGE + e];
        int pos = atomicAdd(&d_cursor[dst], 1);
        d_ebin[pos] = src;
    }
}

// ---------------- mean aggregation: one warp per dst node ----------------
__global__ void k_agg(const float* __restrict__ x) {
    int warp = (blockIdx.x * blockDim.x + threadIdx.x) >> 5;
    int lane = threadIdx.x & 31;
    if (warp >= NTN) return;
    int beg = d_offs[warp], end = d_offs[warp + 1];
    const float4* x4 = (const float4*)x;
    float4 acc = make_float4(0.f, 0.f, 0.f, 0.f);
    for (int e = beg; e < end; e++) {
        int s = __ldg(&d_ebin[e]);
        float4 v = x4[(size_t)s * 32 + lane];
        acc.x += v.x; acc.y += v.y; acc.z += v.z; acc.w += v.w;
    }
    int deg = end - beg;
    float inv = 1.f / (float)(deg > 0 ? deg : 1);
    acc.x *= inv; acc.y *= inv; acc.z *= inv; acc.w *= inv;
    ((float4*)d_agg)[(size_t)warp * 32 + lane] = acc;
}

// ---------------- generic SGEMM: out[M,NC] = A[M,K] @ W[NC,K]^T + bias (+resid)(+relu) ----------------
__global__ void __launch_bounds__(256) k_gemm(
    const float* __restrict__ A, const float* __restrict__ W,
    const float* __restrict__ bias, const float* __restrict__ resid,
    float* __restrict__ out, int M, int NC, int K, int relu)
{
    __shared__ float As[16][68];
    __shared__ float Bs[16][68];
    int row0 = blockIdx.x * 64;
    int col0 = blockIdx.y * 64;
    int tid = threadIdx.x;
    int tx = tid & 15, ty = tid >> 4;
    int tm0 = ty * 4, tn0 = tx * 4;
    float acc[4][4] = {};
    for (int kb = 0; kb < K; kb += 16) {
        #pragma unroll
        for (int it = 0; it < 4; it++) {
            int idx = tid + it * 256;       // 0..1023
            int m = idx >> 4, k = idx & 15;
            As[k][m] = A[(size_t)(row0 + m) * K + kb + k];
            Bs[k][m] = W[(size_t)(col0 + m) * K + kb + k];
        }
        __syncthreads();
        #pragma unroll
        for (int k = 0; k < 16; k++) {
            float4 a = *(const float4*)&As[k][tm0];
            float4 b = *(const float4*)&Bs[k][tn0];
            acc[0][0] = fmaf(a.x, b.x, acc[0][0]);
            acc[0][1] = fmaf(a.x, b.y, acc[0][1]);
            acc[0][2] = fmaf(a.x, b.z, acc[0][2]);
            acc[0][3] = fmaf(a.x, b.w, acc[0][3]);
            acc[1][0] = fmaf(a.y, b.x, acc[1][0]);
            acc[1][1] = fmaf(a.y, b.y, acc[1][1]);
            acc[1][2] = fmaf(a.y, b.z, acc[1][2]);
            acc[1][3] = fmaf(a.y, b.w, acc[1][3]);
            acc[2][0] = fmaf(a.z, b.x, acc[2][0]);
            acc[2][1] = fmaf(a.z, b.y, acc[2][1]);
            acc[2][2] = fmaf(a.z, b.z, acc[2][2]);
            acc[2][3] = fmaf(a.z, b.w, acc[2][3]);
            acc[3][0] = fmaf(a.w, b.x, acc[3][0]);
            acc[3][1] = fmaf(a.w, b.y, acc[3][1]);
            acc[3][2] = fmaf(a.w, b.z, acc[3][2]);
            acc[3][3] = fmaf(a.w, b.w, acc[3][3]);
        }
        __syncthreads();
    }
    float4 bv = *(const float4*)&bias[col0 + tn0];
    #pragma unroll
    for (int i = 0; i < 4; i++) {
        int r = row0 + tm0 + i;
        float4 v;
        v.x = acc[i][0] + bv.x;
        v.y = acc[i][1] + bv.y;
        v.z = acc[i][2] + bv.z;
        v.w = acc[i][3] + bv.w;
        if (resid) {
            float4 rr = *(const float4*)&resid[(size_t)r * NC + col0 + tn0];
            v.x += rr.x; v.y += rr.y; v.z += rr.z; v.w += rr.w;
        }
        if (relu) {
            v.x = fmaxf(v.x, 0.f); v.y = fmaxf(v.y, 0.f);
            v.z = fmaxf(v.z, 0.f); v.w = fmaxf(v.w, 0.f);
        }
        *(float4*)&out[(size_t)r * NC + col0 + tn0] = v;
    }
}

// ---------------- column stats (sum, sumsq) for BN over [NTN,128] ----------------
__global__ void k_stats(const float* __restrict__ src, float* __restrict__ sum,
                        float* __restrict__ sumsq)
{
    int c = threadIdx.x;            // 128 threads
    int r0 = blockIdx.x * 128;      // 128 rows per block
    float s = 0.f, q = 0.f;
    for (int r = 0; r < 128; r++) {
        float v = src[(size_t)(r0 + r) * CCH + c];
        s += v;
        q = fmaf(v, v, q);
    }
    atomicAdd(&sum[c], s);
    atomicAdd(&sumsq[c], q);
}

// ---------------- attention: one CTA per (b, h, half); K/V tiled through static smem ----------------
#define KTILE 128
__global__ void __launch_bounds__(256) k_attn(const float* __restrict__ qkv,
                                              float* __restrict__ ao)
{
    __shared__ float k_s[KTILE * DHEAD];   // 16 KB
    __shared__ float v_s[KTILE * DHEAD];   // 16 KB
    int bh = blockIdx.x >> 1;
    int half = blockIdx.x & 1;
    int b = bh >> 2;
    int h = bh & 3;
    int t = threadIdx.x;
    const float* base = qkv + (size_t)b * NNODE * (3 * CCH);

    // load this thread's q row
    int qr = half * 256 + t;
    float q[32];
    {
        const float4* qsrc = (const float4*)(base + (size_t)qr * (3 * CCH) + h * DHEAD);
        #pragma unroll
        for (int i = 0; i < 8; i++) {
            float4 f = qsrc[i];
            q[4 * i] = f.x; q[4 * i + 1] = f.y; q[4 * i + 2] = f.z; q[4 * i + 3] = f.w;
        }
    }

    float m = -1e30f, l = 0.f, o[32];
    #pragma unroll
    for (int i = 0; i < 32; i++) o[i] = 0.f;

    for (int t0 = 0; t0 < NNODE; t0 += KTILE) {
        // cooperative tile load: 128 rows, 2 threads per row (4 float4 each)
        {
            int r = t >> 1;            // 0..127
            int part = t & 1;          // half-row
            const float4* ksrc = (const float4*)(base + (size_t)(t0 + r) * (3 * CCH) + CCH + h * DHEAD);
            const float4* vsrc = (const float4*)(base + (size_t)(t0 + r) * (3 * CCH) + 2 * CCH + h * DHEAD);
            float4* kd = (float4*)(k_s + r * DHEAD);
            float4* vd = (float4*)(v_s + r * DHEAD);
            #pragma unroll
            for (int i = 0; i < 4; i++) {
                kd[part * 4 + i] = ksrc[part * 4 + i];
                vd[part * 4 + i] = vsrc[part * 4 + i];
            }
        }
        __syncthreads();

        for (int j = 0; j < KTILE; j++) {
            const float4* kr = (const float4*)(k_s + j * DHEAD);
            float s0 = 0.f, s1 = 0.f, s2 = 0.f, s3 = 0.f;
            #pragma unroll
            for (int i = 0; i < 8; i++) {
                float4 kk = kr[i];
                s0 = fmaf(q[4 * i],     kk.x, s0);
                s1 = fmaf(q[4 * i + 1], kk.y, s1);
                s2 = fmaf(q[4 * i + 2], kk.z, s2);
                s3 = fmaf(q[4 * i + 3], kk.w, s3);
            }
            float s = ((s0 + s1) + (s2 + s3)) * 0.1767766952966369f;  // 1/sqrt(32)
            if (s > m) {
                float c = __expf(m - s);
                m = s;
                l *= c;
                #pragma unroll
                for (int i = 0; i < 32; i++) o[i] *= c;
            }
            float p = __expf(s - m);
            l += p;
            const float4* vr = (const float4*)(v_s + j * DHEAD);
            #pragma unroll
            for (int i = 0; i < 8; i++) {
                float4 vv = vr[i];
                o[4 * i]     = fmaf(p, vv.x, o[4 * i]);
                o[4 * i + 1] = fmaf(p, vv.y, o[4 * i + 1]);
                o[4 * i + 2] = fmaf(p, vv.z, o[4 * i + 2]);
                o[4 * i + 3] = fmaf(p, vv.w, o[4 * i + 3]);
            }
        }
        __syncthreads();
    }

    float inv = 1.f / l;
    float4* dst = (float4*)(ao + ((size_t)(b * NNODE + qr)) * CCH + h * DHEAD);
    #pragma unroll
    for (int i = 0; i < 8; i++) {
        float4 f;
        f.x = o[4 * i] * inv;
        f.y = o[4 * i + 1] * inv;
        f.z = o[4 * i + 2] * inv;
        f.w = o[4 * i + 3] * inv;
        dst[i] = f;
    }
}

// ---------------- combine: out1 = BN1(h1) + BN2(h2) ----------------
__global__ void k_combine(const float* __restrict__ h1, const float* __restrict__ h2,
                          const float* __restrict__ g1, const float* __restrict__ b1,
                          const float* __restrict__ g2, const float* __restrict__ b2,
                          float* __restrict__ out1)
{
    int i = blockIdx.x * blockDim.x + threadIdx.x;   // float4 index
    if (i >= NTN * CCH / 4) return;
    int c0 = (i & 31) * 4;
    float4 a = ((const float4*)h1)[i];
    float4 bb = ((const float4*)h2)[i];
    float av[4] = { a.x, a.y, a.z, a.w };
    float bv[4] = { bb.x, bb.y, bb.z, bb.w };
    float rv[4];
    const float invn = 1.f / (float)NTN;
    #pragma unroll
    for (int j = 0; j < 4; j++) {
        int c = c0 + j;
        float m1 = d_stats[c] * invn;
        float v1 = d_stats[CCH + c] * invn - m1 * m1;
        float k1 = rsqrtf(v1 + EPSBN) * g1[c];
        float m2 = d_stats[2 * CCH + c] * invn;
        float v2 = d_stats[3 * CCH + c] * invn - m2 * m2;
        float k2 = rsqrtf(v2 + EPSBN) * g2[c];
        rv[j] = (av[j] - m1) * k1 + b1[c] + (bv[j] - m2) * k2 + b2[c];
    }
    ((float4*)out1)[i] = make_float4(rv[0], rv[1], rv[2], rv[3]);
}

// ---------------- final: out = BN3(out2) ----------------
__global__ void k_final(const float* __restrict__ src,
                        const float* __restrict__ g3, const float* __restrict__ b3,
                        float* __restrict__ out)
{
    int i = blockIdx.x * blockDim.x + threadIdx.x;
    if (i >= NTN * CCH / 4) return;
    int c0 = (i & 31) * 4;
    float4 a = ((const float4*)src)[i];
    float av[4] = { a.x, a.y, a.z, a.w };
    float rv[4];
    const float invn = 1.f / (float)NTN;
    #pragma unroll
    for (int j = 0; j < 4; j++) {
        int c = c0 + j;
        float m = d_stats[4 * CCH + c] * invn;
        float v = d_stats[5 * CCH + c] * invn - m * m;
        float k = rsqrtf(v + EPSBN) * g3[c];
        rv[j] = (av[j] - m) * k + b3[c];
    }
    ((float4*)out)[i] = make_float4(rv[0], rv[1], rv[2], rv[3]);
}

// ---------------- host launcher ----------------
extern "C" void kernel_launch(void* const* d_in, const int* in_sizes, int n_in,
                              void* d_out, int out_size)
{
    const float* x    = (const float*)d_in[0];
    const int*   ei   = (const int*)d_in[1];
    const float* Wc   = (const float*)d_in[2];
    const float* bc   = (const float*)d_in[3];
    const float* Winp = (const float*)d_in[4];
    const float* binp = (const float*)d_in[5];
    const float* Wout = (const float*)d_in[6];
    const float* bout = (const float*)d_in[7];
    const float* gn1  = (const float*)d_in[8];
    const float* bn1  = (const float*)d_in[9];
    const float* gn2  = (const float*)d_in[10];
    const float* bn2  = (const float*)d_in[11];
    const float* gn3  = (const float*)d_in[12];
    const float* bn3  = (const float*)d_in[13];
    const float* Wm1  = (const float*)d_in[14];
    const float* bm1  = (const float*)d_in[15];
    const float* Wm2  = (const float*)d_in[16];
    const float* bm2  = (const float*)d_in[17];
    float* out = (float*)d_out;

    float *agg, *h1, *qkv, *ao, *h2, *out1, *hid, *out2, *stats;
    cudaGetSymbolAddress((void**)&agg,  d_agg);
    cudaGetSymbolAddress((void**)&h1,   d_h1);
    cudaGetSymbolAddress((void**)&qkv,  d_qkv);
    cudaGetSymbolAddress((void**)&ao,   d_ao);
    cudaGetSymbolAddress((void**)&h2,   d_h2);
    cudaGetSymbolAddress((void**)&out1, d_out1);
    cudaGetSymbolAddress((void**)&hid,  d_hid);
    cudaGetSymbolAddress((void**)&out2, d_out2);
    cudaGetSymbolAddress((void**)&stats, d_stats);

    // --- edge CSR + mean aggregation ---
    k_init<<<NTN / 256, 256>>>();
    k_count<<<NEDGE / 256, 256>>>(ei);
    k_scan<<<1, 1024>>>();
    k_bin<<<NEDGE / 256, 256>>>(ei);
    k_agg<<<NTN * 32 / 256, 256>>>(x);

    // --- local branch: h1 = agg @ Wc^T + bc + x ; stats1 ---
    k_gemm<<<dim3(NTN / 64, 2), 256>>>(agg, Wc, bc, x, h1, NTN, 128, 128, 0);
    k_stats<<<NTN / 128, 128>>>(h1, stats, stats + CCH);

    // --- global branch: qkv, attention, out_proj ; stats2 ---
    k_gemm<<<dim3(NTN / 64, 6), 256>>>(x, Winp, binp, nullptr, qkv, NTN, 384, 128, 0);
    k_attn<<<BATCH * NH * 2, 256>>>(qkv, ao);
    k_gemm<<<dim3(NTN / 64, 2), 256>>>(ao, Wout, bout, x, h2, NTN, 128, 128, 0);
    k_stats<<<NTN / 128, 128>>>(h2, stats + 2 * CCH, stats + 3 * CCH);

    // --- combine + MLP + final BN ---
    k_combine<<<NTN * CCH / 4 / 256, 256>>>(h1, h2, gn1, bn1, gn2, bn2, out1);
    k_gemm<<<dim3(NTN / 64, 4), 256>>>(out1, Wm1, bm1, nullptr, hid, NTN, 256, 128, 1);
    k_gemm<<<dim3(NTN / 64, 2), 256>>>(hid, Wm2, bm2, out1, out2, NTN, 128, 256, 0);
    k_stats<<<NTN / 128, 128>>>(out2, stats + 4 * CCH, stats + 5 * CCH);
    k_final<<<NTN * CCH / 4 / 256, 256>>>(out2, gn3, bn3, out);
}

// round 4
// speedup vs baseline: 1.2346x; 1.2346x over previous
#include <cuda_runtime.h>
#include <cstdint>
#include <cstddef>

#define NTN   32768
#define CCH   128
#define BATCH 64
#define NNODE 512
#define NH    4
#define DHEAD 32
#define NEDGE 524288
#define EPSBN 1e-5f

// ---------------- scratch (static device globals; no allocation) ----------------
__device__ int   d_cnt[NTN];
__device__ int   d_offs[NTN + 1];
__device__ int   d_cursor[NTN];
__device__ int   d_ebin[NEDGE];
__device__ float d_agg[NTN * CCH];
__device__ float d_h1[NTN * CCH];
__device__ float d_qkv[NTN * 3 * CCH];
__device__ float d_ao[NTN * CCH];
__device__ float d_h2[NTN * CCH];
__device__ float d_out1[NTN * CCH];
__device__ float d_hid[NTN * 2 * CCH];
__device__ float d_out2[NTN * CCH];
__device__ float d_stats[6 * CCH];   // [sum1, sq1, sum2, sq2, sum3, sq3]

// ---------------- init: zero counters + stats ----------------
__global__ void k_init() {
    int i = blockIdx.x * blockDim.x + threadIdx.x;
    if (i < NTN) d_cnt[i] = 0;
    if (i < 6 * CCH) d_stats[i] = 0.f;
}

// ---------------- edge degree count ----------------
__global__ void k_count(const int* __restrict__ ei) {
    int e = blockIdx.x * blockDim.x + threadIdx.x;
    if (e < NEDGE) atomicAdd(&d_cnt[ei[NEDGE + e]], 1);
}

// ---------------- exclusive scan of degrees (single CTA, 1024 thr x 32) ----------------
__global__ void k_scan() {
    __shared__ int part[1024];
    int tid = threadIdx.x;
    int base = tid * 32;
    int local[32];
    int s = 0;
    #pragma unroll
    for (int i = 0; i < 32; i++) { local[i] = d_cnt[base + i]; s += local[i]; }
    part[tid] = s;
    __syncthreads();
    for (int off = 1; off < 1024; off <<= 1) {
        int v = (tid >= off) ? part[tid - off] : 0;
        __syncthreads();
        part[tid] += v;
        __syncthreads();
    }
    int run = (tid == 0) ? 0 : part[tid - 1];
    #pragma unroll
    for (int i = 0; i < 32; i++) {
        d_offs[base + i] = run;
        d_cursor[base + i] = run;
        run += local[i];
    }
    if (tid == 1023) d_offs[NTN] = run;
}

// ---------------- bin edges by dst ----------------
__global__ void k_bin(const int* __restrict__ ei) {
    int e = blockIdx.x * blockDim.x + threadIdx.x;
    if (e < NEDGE) {
        int src = ei[e];
        int dst = ei[NEDGE + e];
        int pos = atomicAdd(&d_cursor[dst], 1);
        d_ebin[pos] = src;
    }
}

// ---------------- mean aggregation: one warp per dst node ----------------
__global__ void k_agg(const float* __restrict__ x) {
    int warp = (blockIdx.x * blockDim.x + threadIdx.x) >> 5;
    int lane = threadIdx.x & 31;
    if (warp >= NTN) return;
    int beg = d_offs[warp], end = d_offs[warp + 1];
    const float4* x4 = (const float4*)x;
    float4 acc = make_float4(0.f, 0.f, 0.f, 0.f);
    for (int e = beg; e < end; e++) {
        int s = __ldg(&d_ebin[e]);
        float4 v = x4[(size_t)s * 32 + lane];
        acc.x += v.x; acc.y += v.y; acc.z += v.z; acc.w += v.w;
    }
    int deg = end - beg;
    float inv = 1.f / (float)(deg > 0 ? deg : 1);
    acc.x *= inv; acc.y *= inv; acc.z *= inv; acc.w *= inv;
    ((float4*)d_agg)[(size_t)warp * 32 + lane] = acc;
}

// ---------------- tf32 helper ----------------
__device__ __forceinline__ float to_tf32(float x) {
    uint32_t u;
    asm("cvt.rna.tf32.f32 %0, %1;" : "=r"(u) : "f"(x));
    return __uint_as_float(u);
}

// ---------------- tf32 tensor-core GEMM ----------------
// out[M,NC] = A[M,K] @ W[NC,K]^T + bias (+resid)(+relu)
// CTA tile 128x64, BK=32, 8 warps (2x4), warp tile 64x16.
#define BM 128
#define BNT 64
#define BK 32
__global__ void __launch_bounds__(256) k_gemm_tc(
    const float* __restrict__ A, const float* __restrict__ W,
    const float* __restrict__ bias, const float* __restrict__ resid,
    float* __restrict__ out, int M, int NC, int K, int relu)
{
    __shared__ float As[BM][BK + 4];
    __shared__ float Bs[BNT][BK + 4];
    int row0 = blockIdx.x * BM;
    int col0 = blockIdx.y * BNT;
    int tid = threadIdx.x;
    int wid = tid >> 5;
    int lane = tid & 31;
    int g = lane >> 2, tg = lane & 3;
    int wm = (wid & 1) * 64;          // 2 warp-rows of 64
    int wn = (wid >> 1) * 16;         // 4 warp-cols of 16

    float c[4][2][4];
    #pragma unroll
    for (int i = 0; i < 4; i++)
        #pragma unroll
        for (int j = 0; j < 2; j++)
            #pragma unroll
            for (int l = 0; l < 4; l++) c[i][j][l] = 0.f;

    for (int kb = 0; kb < K; kb += BK) {
        // fill As: 128 rows x 8 kquads, coalesced float4
        #pragma unroll
        for (int it = 0; it < 4; it++) {
            int idx = tid + it * 256;
            int m = idx >> 3, kq = idx & 7;
            float4 v = *(const float4*)&A[(size_t)(row0 + m) * K + kb + kq * 4];
            v.x = to_tf32(v.x); v.y = to_tf32(v.y);
            v.z = to_tf32(v.z); v.w = to_tf32(v.w);
            *(float4*)&As[m][kq * 4] = v;
        }
        // fill Bs: 64 rows x 8 kquads
        #pragma unroll
        for (int it = 0; it < 2; it++) {
            int idx = tid + it * 256;
            int n = idx >> 3, kq = idx & 7;
            float4 v = *(const float4*)&W[(size_t)(col0 + n) * K + kb + kq * 4];
            v.x = to_tf32(v.x); v.y = to_tf32(v.y);
            v.z = to_tf32(v.z); v.w = to_tf32(v.w);
            *(float4*)&Bs[n][kq * 4] = v;
        }
        __syncthreads();
        #pragma unroll
        for (int ks = 0; ks < 4; ks++) {
            int k0 = ks * 8;
            uint32_t b[2][2];
            #pragma unroll
            for (int nt = 0; nt < 2; nt++) {
                int n = wn + nt * 8 + g;
                b[nt][0] = __float_as_uint(Bs[n][k0 + tg]);
                b[nt][1] = __float_as_uint(Bs[n][k0 + tg + 4]);
            }
            #pragma unroll
            for (int mt = 0; mt < 4; mt++) {
                int m = wm + mt * 16 + g;
                uint32_t a0 = __float_as_uint(As[m][k0 + tg]);
                uint32_t a1 = __float_as_uint(As[m + 8][k0 + tg]);
                uint32_t a2 = __float_as_uint(As[m][k0 + tg + 4]);
                uint32_t a3 = __float_as_uint(As[m + 8][k0 + tg + 4]);
                #pragma unroll
                for (int nt = 0; nt < 2; nt++) {
                    asm volatile(
                        "mma.sync.aligned.m16n8k8.row.col.f32.tf32.tf32.f32 "
                        "{%0,%1,%2,%3}, {%4,%5,%6,%7}, {%8,%9}, {%0,%1,%2,%3};"
                        : "+f"(c[mt][nt][0]), "+f"(c[mt][nt][1]),
                          "+f"(c[mt][nt][2]), "+f"(c[mt][nt][3])
                        : "r"(a0), "r"(a1), "r"(a2), "r"(a3),
                          "r"(b[nt][0]), "r"(b[nt][1]));
                }
            }
        }
        __syncthreads();
    }

    // epilogue: c0,c1 -> (row g, cols 2tg,2tg+1); c2,c3 -> (row g+8)
    #pragma unroll
    for (int mt = 0; mt < 4; mt++) {
        #pragma unroll
        for (int nt = 0; nt < 2; nt++) {
            int r = row0 + wm + mt * 16 + g;
            int cc = col0 + wn + nt * 8 + 2 * tg;
            float2 bv = *(const float2*)&bias[cc];
            float v0 = c[mt][nt][0] + bv.x;
            float v1 = c[mt][nt][1] + bv.y;
            float v2 = c[mt][nt][2] + bv.x;
            float v3 = c[mt][nt][3] + bv.y;
            if (resid) {
                float2 r0v = *(const float2*)&resid[(size_t)r * NC + cc];
                float2 r1v = *(const float2*)&resid[(size_t)(r + 8) * NC + cc];
                v0 += r0v.x; v1 += r0v.y; v2 += r1v.x; v3 += r1v.y;
            }
            if (relu) {
                v0 = fmaxf(v0, 0.f); v1 = fmaxf(v1, 0.f);
                v2 = fmaxf(v2, 0.f); v3 = fmaxf(v3, 0.f);
            }
            *(float2*)&out[(size_t)r * NC + cc] = make_float2(v0, v1);
            *(float2*)&out[(size_t)(r + 8) * NC + cc] = make_float2(v2, v3);
        }
    }
}

// ---------------- column stats (sum, sumsq) for BN over [NTN,128] ----------------
__global__ void k_stats(const float* __restrict__ src, float* __restrict__ sum,
                        float* __restrict__ sumsq)
{
    int c = threadIdx.x;            // 128 threads
    int r0 = blockIdx.x * 128;      // 128 rows per block
    float s = 0.f, q = 0.f;
    for (int r = 0; r < 128; r++) {
        float v = src[(size_t)(r0 + r) * CCH + c];
        s += v;
        q = fmaf(v, v, q);
    }
    atomicAdd(&sum[c], s);
    atomicAdd(&sumsq[c], q);
}

// ---------------- attention: one CTA per (b, h, half); K/V tiled through static smem ----------------
#define KTILE 128
__global__ void __launch_bounds__(256) k_attn(const float* __restrict__ qkv,
                                              float* __restrict__ ao)
{
    __shared__ float k_s[KTILE * DHEAD];   // 16 KB
    __shared__ float v_s[KTILE * DHEAD];   // 16 KB
    int bh = blockIdx.x >> 1;
    int half = blockIdx.x & 1;
    int b = bh >> 2;
    int h = bh & 3;
    int t = threadIdx.x;
    const float* base = qkv + (size_t)b * NNODE * (3 * CCH);

    int qr = half * 256 + t;
    float q[32];
    {
        const float4* qsrc = (const float4*)(base + (size_t)qr * (3 * CCH) + h * DHEAD);
        #pragma unroll
        for (int i = 0; i < 8; i++) {
            float4 f = qsrc[i];
            q[4 * i] = f.x; q[4 * i + 1] = f.y; q[4 * i + 2] = f.z; q[4 * i + 3] = f.w;
        }
    }

    float m = -1e30f, l = 0.f, o[32];
    #pragma unroll
    for (int i = 0; i < 32; i++) o[i] = 0.f;

    for (int t0 = 0; t0 < NNODE; t0 += KTILE) {
        {
            int r = t >> 1;
            int part = t & 1;
            const float4* ksrc = (const float4*)(base + (size_t)(t0 + r) * (3 * CCH) + CCH + h * DHEAD);
            const float4* vsrc = (const float4*)(base + (size_t)(t0 + r) * (3 * CCH) + 2 * CCH + h * DHEAD);
            float4* kd = (float4*)(k_s + r * DHEAD);
            float4* vd = (float4*)(v_s + r * DHEAD);
            #pragma unroll
            for (int i = 0; i < 4; i++) {
                kd[part * 4 + i] = ksrc[part * 4 + i];
                vd[part * 4 + i] = vsrc[part * 4 + i];
            }
        }
        __syncthreads();

        for (int j = 0; j < KTILE; j++) {
            const float4* kr = (const float4*)(k_s + j * DHEAD);
            float s0 = 0.f, s1 = 0.f, s2 = 0.f, s3 = 0.f;
            #pragma unroll
            for (int i = 0; i < 8; i++) {
                float4 kk = kr[i];
                s0 = fmaf(q[4 * i],     kk.x, s0);
                s1 = fmaf(q[4 * i + 1], kk.y, s1);
                s2 = fmaf(q[4 * i + 2], kk.z, s2);
                s3 = fmaf(q[4 * i + 3], kk.w, s3);
            }
            float s = ((s0 + s1) + (s2 + s3)) * 0.1767766952966369f;  // 1/sqrt(32)
            if (s > m) {
                float cc = __expf(m - s);
                m = s;
                l *= cc;
                #pragma unroll
                for (int i = 0; i < 32; i++) o[i] *= cc;
            }
            float p = __expf(s - m);
            l += p;
            const float4* vr = (const float4*)(v_s + j * DHEAD);
            #pragma unroll
            for (int i = 0; i < 8; i++) {
                float4 vv = vr[i];
                o[4 * i]     = fmaf(p, vv.x, o[4 * i]);
                o[4 * i + 1] = fmaf(p, vv.y, o[4 * i + 1]);
                o[4 * i + 2] = fmaf(p, vv.z, o[4 * i + 2]);
                o[4 * i + 3] = fmaf(p, vv.w, o[4 * i + 3]);
            }
        }
        __syncthreads();
    }

    float inv = 1.f / l;
    float4* dst = (float4*)(ao + ((size_t)(b * NNODE + qr)) * CCH + h * DHEAD);
    #pragma unroll
    for (int i = 0; i < 8; i++) {
        float4 f;
        f.x = o[4 * i] * inv;
        f.y = o[4 * i + 1] * inv;
        f.z = o[4 * i + 2] * inv;
        f.w = o[4 * i + 3] * inv;
        dst[i] = f;
    }
}

// ---------------- combine: out1 = BN1(h1) + BN2(h2) ----------------
__global__ void k_combine(const float* __restrict__ h1, const float* __restrict__ h2,
                          const float* __restrict__ g1, const float* __restrict__ b1,
                          const float* __restrict__ g2, const float* __restrict__ b2,
                          float* __restrict__ out1)
{
    int i = blockIdx.x * blockDim.x + threadIdx.x;   // float4 index
    if (i >= NTN * CCH / 4) return;
    int c0 = (i & 31) * 4;
    float4 a = ((const float4*)h1)[i];
    float4 bb = ((const float4*)h2)[i];
    float av[4] = { a.x, a.y, a.z, a.w };
    float bv[4] = { bb.x, bb.y, bb.z, bb.w };
    float rv[4];
    const float invn = 1.f / (float)NTN;
    #pragma unroll
    for (int j = 0; j < 4; j++) {
        int c = c0 + j;
        float m1 = d_stats[c] * invn;
        float v1 = d_stats[CCH + c] * invn - m1 * m1;
        float k1 = rsqrtf(v1 + EPSBN) * g1[c];
        float m2 = d_stats[2 * CCH + c] * invn;
        float v2 = d_stats[3 * CCH + c] * invn - m2 * m2;
        float k2 = rsqrtf(v2 + EPSBN) * g2[c];
        rv[j] = (av[j] - m1) * k1 + b1[c] + (bv[j] - m2) * k2 + b2[c];
    }
    ((float4*)out1)[i] = make_float4(rv[0], rv[1], rv[2], rv[3]);
}

// ---------------- final: out = BN3(out2) ----------------
__global__ void k_final(const float* __restrict__ src,
                        const float* __restrict__ g3, const float* __restrict__ b3,
                        float* __restrict__ out)
{
    int i = blockIdx.x * blockDim.x + threadIdx.x;
    if (i >= NTN * CCH / 4) return;
    int c0 = (i & 31) * 4;
    float4 a = ((const float4*)src)[i];
    float av[4] = { a.x, a.y, a.z, a.w };
    float rv[4];
    const float invn = 1.f / (float)NTN;
    #pragma unroll
    for (int j = 0; j < 4; j++) {
        int c = c0 + j;
        float m = d_stats[4 * CCH + c] * invn;
        float v = d_stats[5 * CCH + c] * invn - m * m;
        float k = rsqrtf(v + EPSBN) * g3[c];
        rv[j] = (av[j] - m) * k + b3[c];
    }
    ((float4*)out)[i] = make_float4(rv[0], rv[1], rv[2], rv[3]);
}

// ---------------- host launcher ----------------
extern "C" void kernel_launch(void* const* d_in, const int* in_sizes, int n_in,
                              void* d_out, int out_size)
{
    const float* x    = (const float*)d_in[0];
    const int*   ei   = (const int*)d_in[1];
    const float* Wc   = (const float*)d_in[2];
    const float* bc   = (const float*)d_in[3];
    const float* Winp = (const float*)d_in[4];
    const float* binp = (const float*)d_in[5];
    const float* Wout = (const float*)d_in[6];
    const float* bout = (const float*)d_in[7];
    const float* gn1  = (const float*)d_in[8];
    const float* bn1  = (const float*)d_in[9];
    const float* gn2  = (const float*)d_in[10];
    const float* bn2  = (const float*)d_in[11];
    const float* gn3  = (const float*)d_in[12];
    const float* bn3  = (const float*)d_in[13];
    const float* Wm1  = (const float*)d_in[14];
    const float* bm1  = (const float*)d_in[15];
    const float* Wm2  = (const float*)d_in[16];
    const float* bm2  = (const float*)d_in[17];
    float* out = (float*)d_out;

    float *agg, *h1, *qkv, *ao, *h2, *out1, *hid, *out2, *stats;
    cudaGetSymbolAddress((void**)&agg,  d_agg);
    cudaGetSymbolAddress((void**)&h1,   d_h1);
    cudaGetSymbolAddress((void**)&qkv,  d_qkv);
    cudaGetSymbolAddress((void**)&ao,   d_ao);
    cudaGetSymbolAddress((void**)&h2,   d_h2);
    cudaGetSymbolAddress((void**)&out1, d_out1);
    cudaGetSymbolAddress((void**)&hid,  d_hid);
    cudaGetSymbolAddress((void**)&out2, d_out2);
    cudaGetSymbolAddress((void**)&stats, d_stats);

    // --- edge CSR + mean aggregation ---
    k_init<<<NTN / 256, 256>>>();
    k_count<<<NEDGE / 256, 256>>>(ei);
    k_scan<<<1, 1024>>>();
    k_bin<<<NEDGE / 256, 256>>>(ei);
    k_agg<<<NTN * 32 / 256, 256>>>(x);

    // --- local branch: h1 = agg @ Wc^T + bc + x ; stats1 ---
    k_gemm_tc<<<dim3(NTN / BM, 2), 256>>>(agg, Wc, bc, x, h1, NTN, 128, 128, 0);
    k_stats<<<NTN / 128, 128>>>(h1, stats, stats + CCH);

    // --- global branch: qkv, attention, out_proj ; stats2 ---
    k_gemm_tc<<<dim3(NTN / BM, 6), 256>>>(x, Winp, binp, nullptr, qkv, NTN, 384, 128, 0);
    k_attn<<<BATCH * NH * 2, 256>>>(qkv, ao);
    k_gemm_tc<<<dim3(NTN / BM, 2), 256>>>(ao, Wout, bout, x, h2, NTN, 128, 128, 0);
    k_stats<<<NTN / 128, 128>>>(h2, stats + 2 * CCH, stats + 3 * CCH);

    // --- combine + MLP + final BN ---
    k_combine<<<NTN * CCH / 4 / 256, 256>>>(h1, h2, gn1, bn1, gn2, bn2, out1);
    k_gemm_tc<<<dim3(NTN / BM, 4), 256>>>(out1, Wm1, bm1, nullptr, hid, NTN, 256, 128, 1);
    k_gemm_tc<<<dim3(NTN / BM, 2), 256>>>(hid, Wm2, bm2, out1, out2, NTN, 128, 256, 0);
    k_stats<<<NTN / 128, 128>>>(out2, stats + 4 * CCH, stats + 5 * CCH);
    k_final<<<NTN * CCH / 4 / 256, 256>>>(out2, gn3, bn3, out);
}

// round 5
// speedup vs baseline: 2.0716x; 1.6779x over previous
#include <cuda_runtime.h>
#include <cstdint>
#include <cstddef>

#define NTN   32768
#define CCH   128
#define BATCH 64
#define NNODE 512
#define NH    4
#define DHEAD 32
#define NEDGE 524288
#define EPSBN 1e-5f

// ---------------- scratch (static device globals; no allocation) ----------------
__device__ int   d_cnt[NTN];
__device__ int   d_offs[NTN + 1];
__device__ int   d_cursor[NTN];
__device__ int   d_ebin[NEDGE];
__device__ float d_agg[NTN * CCH];
__device__ float d_h1[NTN * CCH];
__device__ float d_qkv[NTN * 3 * CCH];
__device__ float d_ao[NTN * CCH];
__device__ float d_h2[NTN * CCH];
__device__ float d_out1[NTN * CCH];
__device__ float d_hid[NTN * 2 * CCH];
__device__ float d_out2[NTN * CCH];
__device__ float d_stats[6 * CCH];

// ---------------- init ----------------
__global__ void k_init() {
    int i = blockIdx.x * blockDim.x + threadIdx.x;
    if (i < NTN) d_cnt[i] = 0;
    if (i < 6 * CCH) d_stats[i] = 0.f;
}

__global__ void k_count(const int* __restrict__ ei) {
    int e = blockIdx.x * blockDim.x + threadIdx.x;
    if (e < NEDGE) atomicAdd(&d_cnt[ei[NEDGE + e]], 1);
}

__global__ void k_scan() {
    __shared__ int part[1024];
    int tid = threadIdx.x;
    int base = tid * 32;
    int local[32];
    int s = 0;
    #pragma unroll
    for (int i = 0; i < 32; i++) { local[i] = d_cnt[base + i]; s += local[i]; }
    part[tid] = s;
    __syncthreads();
    for (int off = 1; off < 1024; off <<= 1) {
        int v = (tid >= off) ? part[tid - off] : 0;
        __syncthreads();
        part[tid] += v;
        __syncthreads();
    }
    int run = (tid == 0) ? 0 : part[tid - 1];
    #pragma unroll
    for (int i = 0; i < 32; i++) {
        d_offs[base + i] = run;
        d_cursor[base + i] = run;
        run += local[i];
    }
    if (tid == 1023) d_offs[NTN] = run;
}

__global__ void k_bin(const int* __restrict__ ei) {
    int e = blockIdx.x * blockDim.x + threadIdx.x;
    if (e < NEDGE) {
        int src = ei[e];
        int dst = ei[NEDGE + e];
        int pos = atomicAdd(&d_cursor[dst], 1);
        d_ebin[pos] = src;
    }
}

__global__ void k_agg(const float* __restrict__ x) {
    int warp = (blockIdx.x * blockDim.x + threadIdx.x) >> 5;
    int lane = threadIdx.x & 31;
    if (warp >= NTN) return;
    int beg = d_offs[warp], end = d_offs[warp + 1];
    const float4* x4 = (const float4*)x;
    float4 acc = make_float4(0.f, 0.f, 0.f, 0.f);
    for (int e = beg; e < end; e++) {
        int s = __ldg(&d_ebin[e]);
        float4 v = x4[(size_t)s * 32 + lane];
        acc.x += v.x; acc.y += v.y; acc.z += v.z; acc.w += v.w;
    }
    int deg = end - beg;
    float inv = 1.f / (float)(deg > 0 ? deg : 1);
    acc.x *= inv; acc.y *= inv; acc.z *= inv; acc.w *= inv;
    ((float4*)d_agg)[(size_t)warp * 32 + lane] = acc;
}

// ---------------- tf32 helper ----------------
__device__ __forceinline__ float to_tf32(float x) {
    uint32_t u;
    asm("cvt.rna.tf32.f32 %0, %1;" : "=r"(u) : "f"(x));
    return __uint_as_float(u);
}

// ---------------- tf32 tensor-core GEMM (validated R4) ----------------
#define BM 128
#define BNT 64
#define BK 32
__global__ void __launch_bounds__(256) k_gemm_tc(
    const float* __restrict__ A, const float* __restrict__ W,
    const float* __restrict__ bias, const float* __restrict__ resid,
    float* __restrict__ out, int M, int NC, int K, int relu)
{
    __shared__ float As[BM][BK + 4];
    __shared__ float Bs[BNT][BK + 4];
    int row0 = blockIdx.x * BM;
    int col0 = blockIdx.y * BNT;
    int tid = threadIdx.x;
    int wid = tid >> 5;
    int lane = tid & 31;
    int g = lane >> 2, tg = lane & 3;
    int wm = (wid & 1) * 64;
    int wn = (wid >> 1) * 16;

    float c[4][2][4];
    #pragma unroll
    for (int i = 0; i < 4; i++)
        #pragma unroll
        for (int j = 0; j < 2; j++)
            #pragma unroll
            for (int l = 0; l < 4; l++) c[i][j][l] = 0.f;

    for (int kb = 0; kb < K; kb += BK) {
        #pragma unroll
        for (int it = 0; it < 4; it++) {
            int idx = tid + it * 256;
            int m = idx >> 3, kq = idx & 7;
            float4 v = *(const float4*)&A[(size_t)(row0 + m) * K + kb + kq * 4];
            v.x = to_tf32(v.x); v.y = to_tf32(v.y);
            v.z = to_tf32(v.z); v.w = to_tf32(v.w);
            *(float4*)&As[m][kq * 4] = v;
        }
        #pragma unroll
        for (int it = 0; it < 2; it++) {
            int idx = tid + it * 256;
            int n = idx >> 3, kq = idx & 7;
            float4 v = *(const float4*)&W[(size_t)(col0 + n) * K + kb + kq * 4];
            v.x = to_tf32(v.x); v.y = to_tf32(v.y);
            v.z = to_tf32(v.z); v.w = to_tf32(v.w);
            *(float4*)&Bs[n][kq * 4] = v;
        }
        __syncthreads();
        #pragma unroll
        for (int ks = 0; ks < 4; ks++) {
            int k0 = ks * 8;
            uint32_t b[2][2];
            #pragma unroll
            for (int nt = 0; nt < 2; nt++) {
                int n = wn + nt * 8 + g;
                b[nt][0] = __float_as_uint(Bs[n][k0 + tg]);
                b[nt][1] = __float_as_uint(Bs[n][k0 + tg + 4]);
            }
            #pragma unroll
            for (int mt = 0; mt < 4; mt++) {
                int m = wm + mt * 16 + g;
                uint32_t a0 = __float_as_uint(As[m][k0 + tg]);
                uint32_t a1 = __float_as_uint(As[m + 8][k0 + tg]);
                uint32_t a2 = __float_as_uint(As[m][k0 + tg + 4]);
                uint32_t a3 = __float_as_uint(As[m + 8][k0 + tg + 4]);
                #pragma unroll
                for (int nt = 0; nt < 2; nt++) {
                    asm volatile(
                        "mma.sync.aligned.m16n8k8.row.col.f32.tf32.tf32.f32 "
                        "{%0,%1,%2,%3}, {%4,%5,%6,%7}, {%8,%9}, {%0,%1,%2,%3};"
                        : "+f"(c[mt][nt][0]), "+f"(c[mt][nt][1]),
                          "+f"(c[mt][nt][2]), "+f"(c[mt][nt][3])
                        : "r"(a0), "r"(a1), "r"(a2), "r"(a3),
                          "r"(b[nt][0]), "r"(b[nt][1]));
                }
            }
        }
        __syncthreads();
    }

    #pragma unroll
    for (int mt = 0; mt < 4; mt++) {
        #pragma unroll
        for (int nt = 0; nt < 2; nt++) {
            int r = row0 + wm + mt * 16 + g;
            int cc = col0 + wn + nt * 8 + 2 * tg;
            float2 bv = *(const float2*)&bias[cc];
            float v0 = c[mt][nt][0] + bv.x;
            float v1 = c[mt][nt][1] + bv.y;
            float v2 = c[mt][nt][2] + bv.x;
            float v3 = c[mt][nt][3] + bv.y;
            if (resid) {
                float2 r0v = *(const float2*)&resid[(size_t)r * NC + cc];
                float2 r1v = *(const float2*)&resid[(size_t)(r + 8) * NC + cc];
                v0 += r0v.x; v1 += r0v.y; v2 += r1v.x; v3 += r1v.y;
            }
            if (relu) {
                v0 = fmaxf(v0, 0.f); v1 = fmaxf(v1, 0.f);
                v2 = fmaxf(v2, 0.f); v3 = fmaxf(v3, 0.f);
            }
            *(float2*)&out[(size_t)r * NC + cc] = make_float2(v0, v1);
            *(float2*)&out[(size_t)(r + 8) * NC + cc] = make_float2(v2, v3);
        }
    }
}

// ---------------- column stats ----------------
__global__ void k_stats(const float* __restrict__ src, float* __restrict__ sum,
                        float* __restrict__ sumsq)
{
    int c = threadIdx.x;
    int r0 = blockIdx.x * 128;
    float s = 0.f, q = 0.f;
    for (int r = 0; r < 128; r++) {
        float v = src[(size_t)(r0 + r) * CCH + c];
        s += v;
        q = fmaf(v, v, q);
    }
    atomicAdd(&sum[c], s);
    atomicAdd(&sumsq[c], q);
}

// ---------------- tensor-core flash attention ----------------
// One CTA per (b, h, qtile of 128). 8 warps x 16 q-rows. K-tiles of 64.
// smem: Ks[64][36] + Vs[64][40] + Ps[8 warps][16][68]  = 54272 B (dynamic)
#define KT 64
#define KS_PAD 36
#define VS_PAD 40
#define PS_PAD 68
#define ATTN_SMEM ((KT * KS_PAD + KT * VS_PAD + 8 * 16 * PS_PAD) * 4)
__global__ void __launch_bounds__(256) k_attn_tc(const float* __restrict__ qkv,
                                                 float* __restrict__ ao)
{
    extern __shared__ float sm[];
    float* Ks = sm;                         // [64][36]
    float* Vs = Ks + KT * KS_PAD;           // [64][40]
    int tid = threadIdx.x;
    int wid = tid >> 5;
    int lane = tid & 31;
    int g = lane >> 2, tg = lane & 3;
    float* Ps = Vs + KT * VS_PAD + wid * 16 * PS_PAD;   // per-warp [16][68]

    int blk = blockIdx.x;          // (b*4 + h)*4 + qt
    int qt = blk & 3;
    int bh = blk >> 2;
    int b = bh >> 2;
    int h = bh & 3;
    const float* base = qkv + (size_t)b * NNODE * (3 * CCH);
    int qrow0 = qt * 128 + wid * 16;
    const float SCALE = 0.1767766952966369f;   // 1/sqrt(32)

    // Q fragments (tf32), 4 k-chunks of 8
    uint32_t qa[4][4];
    #pragma unroll
    for (int kc = 0; kc < 4; kc++) {
        const float* q0 = base + (size_t)(qrow0 + g) * (3 * CCH) + h * DHEAD + 8 * kc;
        const float* q1 = base + (size_t)(qrow0 + g + 8) * (3 * CCH) + h * DHEAD + 8 * kc;
        qa[kc][0] = __float_as_uint(to_tf32(q0[tg]));
        qa[kc][1] = __float_as_uint(to_tf32(q1[tg]));
        qa[kc][2] = __float_as_uint(to_tf32(q0[tg + 4]));
        qa[kc][3] = __float_as_uint(to_tf32(q1[tg + 4]));
    }

    float m0 = -1e30f, m1 = -1e30f, l0 = 0.f, l1 = 0.f;
    float o[4][4];
    #pragma unroll
    for (int i = 0; i < 4; i++)
        #pragma unroll
        for (int j = 0; j < 4; j++) o[i][j] = 0.f;

    for (int kt = 0; kt < NNODE / KT; kt++) {
        // cooperative K/V tile load (tf32-converted)
        #pragma unroll
        for (int it = 0; it < 2; it++) {
            int idx = tid + it * 256;
            int row = idx >> 3;
            int c4 = (idx & 7) * 4;
            const float* krow = base + (size_t)(kt * KT + row) * (3 * CCH) + CCH + h * DHEAD;
            const float* vrow = base + (size_t)(kt * KT + row) * (3 * CCH) + 2 * CCH + h * DHEAD;
            float4 kv = *(const float4*)(krow + c4);
            float4 vv = *(const float4*)(vrow + c4);
            kv.x = to_tf32(kv.x); kv.y = to_tf32(kv.y); kv.z = to_tf32(kv.z); kv.w = to_tf32(kv.w);
            vv.x = to_tf32(vv.x); vv.y = to_tf32(vv.y); vv.z = to_tf32(vv.z); vv.w = to_tf32(vv.w);
            *(float4*)(Ks + row * KS_PAD + c4) = kv;
            *(float4*)(Vs + row * VS_PAD + c4) = vv;
        }
        __syncthreads();

        // S = Q @ K^T  : 8 n-tiles of 8 keys
        float s[8][4];
        #pragma unroll
        for (int nt = 0; nt < 8; nt++)
            #pragma unroll
            for (int j = 0; j < 4; j++) s[nt][j] = 0.f;
        #pragma unroll
        for (int kc = 0; kc < 4; kc++) {
            #pragma unroll
            for (int nt = 0; nt < 8; nt++) {
                uint32_t b0 = __float_as_uint(Ks[(nt * 8 + g) * KS_PAD + 8 * kc + tg]);
                uint32_t b1 = __float_as_uint(Ks[(nt * 8 + g) * KS_PAD + 8 * kc + tg + 4]);
                asm volatile(
                    "mma.sync.aligned.m16n8k8.row.col.f32.tf32.tf32.f32 "
                    "{%0,%1,%2,%3}, {%4,%5,%6,%7}, {%8,%9}, {%0,%1,%2,%3};"
                    : "+f"(s[nt][0]), "+f"(s[nt][1]), "+f"(s[nt][2]), "+f"(s[nt][3])
                    : "r"(qa[kc][0]), "r"(qa[kc][1]), "r"(qa[kc][2]), "r"(qa[kc][3]),
                      "r"(b0), "r"(b1));
            }
        }
        // scale + row max (rows g and g+8)
        float mx0 = -1e30f, mx1 = -1e30f;
        #pragma unroll
        for (int nt = 0; nt < 8; nt++) {
            s[nt][0] *= SCALE; s[nt][1] *= SCALE; s[nt][2] *= SCALE; s[nt][3] *= SCALE;
            mx0 = fmaxf(mx0, fmaxf(s[nt][0], s[nt][1]));
            mx1 = fmaxf(mx1, fmaxf(s[nt][2], s[nt][3]));
        }
        #pragma unroll
        for (int off = 1; off <= 2; off <<= 1) {
            mx0 = fmaxf(mx0, __shfl_xor_sync(0xffffffffu, mx0, off));
            mx1 = fmaxf(mx1, __shfl_xor_sync(0xffffffffu, mx1, off));
        }
        float nm0 = fmaxf(m0, mx0), nm1 = fmaxf(m1, mx1);
        float f0 = __expf(m0 - nm0), f1 = __expf(m1 - nm1);
        m0 = nm0; m1 = nm1;
        // exponentiate + row sums, store tf32 P to smem
        float rs0 = 0.f, rs1 = 0.f;
        #pragma unroll
        for (int nt = 0; nt < 8; nt++) {
            float p0 = __expf(s[nt][0] - m0);
            float p1 = __expf(s[nt][1] - m0);
            float p2 = __expf(s[nt][2] - m1);
            float p3 = __expf(s[nt][3] - m1);
            rs0 += p0 + p1; rs1 += p2 + p3;
            *(float2*)(Ps + g * PS_PAD + nt * 8 + 2 * tg)       = make_float2(to_tf32(p0), to_tf32(p1));
            *(float2*)(Ps + (g + 8) * PS_PAD + nt * 8 + 2 * tg) = make_float2(to_tf32(p2), to_tf32(p3));
        }
        #pragma unroll
        for (int off = 1; off <= 2; off <<= 1) {
            rs0 += __shfl_xor_sync(0xffffffffu, rs0, off);
            rs1 += __shfl_xor_sync(0xffffffffu, rs1, off);
        }
        l0 = l0 * f0 + rs0;
        l1 = l1 * f1 + rs1;
        // rescale O
        #pragma unroll
        for (int nt = 0; nt < 4; nt++) {
            o[nt][0] *= f0; o[nt][1] *= f0; o[nt][2] *= f1; o[nt][3] *= f1;
        }
        __syncwarp();
        // O += P @ V : 8 k-chunks of keys, 4 n-tiles of dh
        #pragma unroll
        for (int kc = 0; kc < 8; kc++) {
            uint32_t a0 = __float_as_uint(Ps[g * PS_PAD + 8 * kc + tg]);
            uint32_t a1 = __float_as_uint(Ps[(g + 8) * PS_PAD + 8 * kc + tg]);
            uint32_t a2 = __float_as_uint(Ps[g * PS_PAD + 8 * kc + tg + 4]);
            uint32_t a3 = __float_as_uint(Ps[(g + 8) * PS_PAD + 8 * kc + tg + 4]);
            #pragma unroll
            for (int nt = 0; nt < 4; nt++) {
                uint32_t b0 = __float_as_uint(Vs[(8 * kc + tg) * VS_PAD + 8 * nt + g]);
                uint32_t b1 = __float_as_uint(Vs[(8 * kc + tg + 4) * VS_PAD + 8 * nt + g]);
                asm volatile(
                    "mma.sync.aligned.m16n8k8.row.col.f32.tf32.tf32.f32 "
                    "{%0,%1,%2,%3}, {%4,%5,%6,%7}, {%8,%9}, {%0,%1,%2,%3};"
                    : "+f"(o[nt][0]), "+f"(o[nt][1]), "+f"(o[nt][2]), "+f"(o[nt][3])
                    : "r"(a0), "r"(a1), "r"(a2), "r"(a3), "r"(b0), "r"(b1));
            }
        }
        __syncthreads();
    }

    // epilogue: divide by l, write rows g and g+8
    float inv0 = 1.f / l0, inv1 = 1.f / l1;
    #pragma unroll
    for (int nt = 0; nt < 4; nt++) {
        int cc = h * DHEAD + nt * 8 + 2 * tg;
        int r0 = b * NNODE + qrow0 + g;
        *(float2*)&ao[(size_t)r0 * CCH + cc] = make_float2(o[nt][0] * inv0, o[nt][1] * inv0);
        *(float2*)&ao[(size_t)(r0 + 8) * CCH + cc] = make_float2(o[nt][2] * inv1, o[nt][3] * inv1);
    }
}

// ---------------- combine: out1 = BN1(h1) + BN2(h2) ----------------
__global__ void k_combine(const float* __restrict__ h1, const float* __restrict__ h2,
                          const float* __restrict__ g1, const float* __restrict__ b1,
                          const float* __restrict__ g2, const float* __restrict__ b2,
                          float* __restrict__ out1)
{
    int i = blockIdx.x * blockDim.x + threadIdx.x;
    if (i >= NTN * CCH / 4) return;
    int c0 = (i & 31) * 4;
    float4 a = ((const float4*)h1)[i];
    float4 bb = ((const float4*)h2)[i];
    float av[4] = { a.x, a.y, a.z, a.w };
    float bv[4] = { bb.x, bb.y, bb.z, bb.w };
    float rv[4];
    const float invn = 1.f / (float)NTN;
    #pragma unroll
    for (int j = 0; j < 4; j++) {
        int c = c0 + j;
        float m1 = d_stats[c] * invn;
        float v1 = d_stats[CCH + c] * invn - m1 * m1;
        float k1 = rsqrtf(v1 + EPSBN) * g1[c];
        float m2 = d_stats[2 * CCH + c] * invn;
        float v2 = d_stats[3 * CCH + c] * invn - m2 * m2;
        float k2 = rsqrtf(v2 + EPSBN) * g2[c];
        rv[j] = (av[j] - m1) * k1 + b1[c] + (bv[j] - m2) * k2 + b2[c];
    }
    ((float4*)out1)[i] = make_float4(rv[0], rv[1], rv[2], rv[3]);
}

// ---------------- final: out = BN3(out2) ----------------
__global__ void k_final(const float* __restrict__ src,
                        const float* __restrict__ g3, const float* __restrict__ b3,
                        float* __restrict__ out)
{
    int i = blockIdx.x * blockDim.x + threadIdx.x;
    if (i >= NTN * CCH / 4) return;
    int c0 = (i & 31) * 4;
    float4 a = ((const float4*)src)[i];
    float av[4] = { a.x, a.y, a.z, a.w };
    float rv[4];
    const float invn = 1.f / (float)NTN;
    #pragma unroll
    for (int j = 0; j < 4; j++) {
        int c = c0 + j;
        float m = d_stats[4 * CCH + c] * invn;
        float v = d_stats[5 * CCH + c] * invn - m * m;
        float k = rsqrtf(v + EPSBN) * g3[c];
        rv[j] = (av[j] - m) * k + b3[c];
    }
    ((float4*)out)[i] = make_float4(rv[0], rv[1], rv[2], rv[3]);
}

// ---------------- host launcher ----------------
extern "C" void kernel_launch(void* const* d_in, const int* in_sizes, int n_in,
                              void* d_out, int out_size)
{
    const float* x    = (const float*)d_in[0];
    const int*   ei   = (const int*)d_in[1];
    const float* Wc   = (const float*)d_in[2];
    const float* bc   = (const float*)d_in[3];
    const float* Winp = (const float*)d_in[4];
    const float* binp = (const float*)d_in[5];
    const float* Wout = (const float*)d_in[6];
    const float* bout = (const float*)d_in[7];
    const float* gn1  = (const float*)d_in[8];
    const float* bn1  = (const float*)d_in[9];
    const float* gn2  = (const float*)d_in[10];
    const float* bn2  = (const float*)d_in[11];
    const float* gn3  = (const float*)d_in[12];
    const float* bn3  = (const float*)d_in[13];
    const float* Wm1  = (const float*)d_in[14];
    const float* bm1  = (const float*)d_in[15];
    const float* Wm2  = (const float*)d_in[16];
    const float* bm2  = (const float*)d_in[17];
    float* out = (float*)d_out;

    float *agg, *h1, *qkv, *ao, *h2, *out1, *hid, *out2, *stats;
    cudaGetSymbolAddress((void**)&agg,  d_agg);
    cudaGetSymbolAddress((void**)&h1,   d_h1);
    cudaGetSymbolAddress((void**)&qkv,  d_qkv);
    cudaGetSymbolAddress((void**)&ao,   d_ao);
    cudaGetSymbolAddress((void**)&h2,   d_h2);
    cudaGetSymbolAddress((void**)&out1, d_out1);
    cudaGetSymbolAddress((void**)&hid,  d_hid);
    cudaGetSymbolAddress((void**)&out2, d_out2);
    cudaGetSymbolAddress((void**)&stats, d_stats);

    cudaFuncSetAttribute(k_attn_tc, cudaFuncAttributeMaxDynamicSharedMemorySize, ATTN_SMEM);

    // --- edge CSR + mean aggregation ---
    k_init<<<NTN / 256, 256>>>();
    k_count<<<NEDGE / 256, 256>>>(ei);
    k_scan<<<1, 1024>>>();
    k_bin<<<NEDGE / 256, 256>>>(ei);
    k_agg<<<NTN * 32 / 256, 256>>>(x);

    // --- local branch ---
    k_gemm_tc<<<dim3(NTN / BM, 2), 256>>>(agg, Wc, bc, x, h1, NTN, 128, 128, 0);
    k_stats<<<NTN / 128, 128>>>(h1, stats, stats + CCH);

    // --- global branch ---
    k_gemm_tc<<<dim3(NTN / BM, 6), 256>>>(x, Winp, binp, nullptr, qkv, NTN, 384, 128, 0);
    k_attn_tc<<<BATCH * NH * 4, 256, ATTN_SMEM>>>(qkv, ao);
    k_gemm_tc<<<dim3(NTN / BM, 2), 256>>>(ao, Wout, bout, x, h2, NTN, 128, 128, 0);
    k_stats<<<NTN / 128, 128>>>(h2, stats + 2 * CCH, stats + 3 * CCH);

    // --- combine + MLP + final BN ---
    k_combine<<<NTN * CCH / 4 / 256, 256>>>(h1, h2, gn1, bn1, gn2, bn2, out1);
    k_gemm_tc<<<dim3(NTN / BM, 4), 256>>>(out1, Wm1, bm1, nullptr, hid, NTN, 256, 128, 1);
    k_gemm_tc<<<dim3(NTN / BM, 2), 256>>>(hid, Wm2, bm2, out1, out2, NTN, 128, 256, 0);
    k_stats<<<NTN / 128, 128>>>(out2, stats + 4 * CCH, stats + 5 * CCH);
    k_final<<<NTN * CCH / 4 / 256, 256>>>(out2, gn3, bn3, out);
}

// round 8
// speedup vs baseline: 2.1268x; 1.0267x over previous
#include <cuda_runtime.h>
#include <cstdint>
#include <cstddef>

#define NTN   32768
#define CCH   128
#define BATCH 64
#define NNODE 512
#define NH    4
#define DHEAD 32
#define NEDGE 524288
#define EPSBN 1e-5f

// ---------------- scratch (static device globals; no allocation) ----------------
__device__ int   d_cnt[NTN];
__device__ int   d_offs[NTN + 1];
__device__ int   d_cursor[NTN];
__device__ int   d_ebin[NEDGE];
__device__ float d_agg[NTN * CCH];
__device__ float d_h1[NTN * CCH];
__device__ float d_qkv[NTN * 3 * CCH];
__device__ float d_ao[NTN * CCH];
__device__ float d_h2[NTN * CCH];
__device__ float d_out1[NTN * CCH];
__device__ float d_hid[NTN * 2 * CCH];
__device__ float d_out2[NTN * CCH];
__device__ float d_stats[6 * CCH];

// ---------------- init ----------------
__global__ void k_init() {
    int i = blockIdx.x * blockDim.x + threadIdx.x;
    if (i < NTN) d_cnt[i] = 0;
    if (i < 6 * CCH) d_stats[i] = 0.f;
}

__global__ void k_count(const int* __restrict__ ei) {
    int e = blockIdx.x * blockDim.x + threadIdx.x;
    if (e < NEDGE) atomicAdd(&d_cnt[ei[NEDGE + e]], 1);
}

__global__ void k_scan() {
    __shared__ int part[1024];
    int tid = threadIdx.x;
    int base = tid * 32;
    int local[32];
    int s = 0;
    #pragma unroll
    for (int i = 0; i < 32; i++) { local[i] = d_cnt[base + i]; s += local[i]; }
    part[tid] = s;
    __syncthreads();
    for (int off = 1; off < 1024; off <<= 1) {
        int v = (tid >= off) ? part[tid - off] : 0;
        __syncthreads();
        part[tid] += v;
        __syncthreads();
    }
    int run = (tid == 0) ? 0 : part[tid - 1];
    #pragma unroll
    for (int i = 0; i < 32; i++) {
        d_offs[base + i] = run;
        d_cursor[base + i] = run;
        run += local[i];
    }
    if (tid == 1023) d_offs[NTN] = run;
}

__global__ void k_bin(const int* __restrict__ ei) {
    int e = blockIdx.x * blockDim.x + threadIdx.x;
    if (e < NEDGE) {
        int src = ei[e];
        int dst = ei[NEDGE + e];
        int pos = atomicAdd(&d_cursor[dst], 1);
        d_ebin[pos] = src;
    }
}

__global__ void k_agg(const float* __restrict__ x) {
    int warp = (blockIdx.x * blockDim.x + threadIdx.x) >> 5;
    int lane = threadIdx.x & 31;
    if (warp >= NTN) return;
    int beg = d_offs[warp], end = d_offs[warp + 1];
    const float4* x4 = (const float4*)x;
    float4 acc = make_float4(0.f, 0.f, 0.f, 0.f);
    for (int e = beg; e < end; e++) {
        int s = __ldg(&d_ebin[e]);
        float4 v = x4[(size_t)s * 32 + lane];
        acc.x += v.x; acc.y += v.y; acc.z += v.z; acc.w += v.w;
    }
    int deg = end - beg;
    float inv = 1.f / (float)(deg > 0 ? deg : 1);
    acc.x *= inv; acc.y *= inv; acc.z *= inv; acc.w *= inv;
    ((float4*)d_agg)[(size_t)warp * 32 + lane] = acc;
}

// ---------------- tf32 helper ----------------
__device__ __forceinline__ float to_tf32(float x) {
    uint32_t u;
    asm("cvt.rna.tf32.f32 %0, %1;" : "=r"(u) : "f"(x));
    return __uint_as_float(u);
}

// ---------------- tf32 GEMM: 128x128 CTA, 64x32 warp tile, reg double-buffer ----------------
// out[M,NC] = A[M,K] @ W[NC,K]^T + bias (+resid)(+relu)(+col stats)
#define GBK 32
__global__ void __launch_bounds__(256) k_gemm2(
    const float* __restrict__ A, const float* __restrict__ W,
    const float* __restrict__ bias, const float* __restrict__ resid,
    float* __restrict__ out, float* __restrict__ ssum, float* __restrict__ ssq,
    int M, int NC, int K, int relu)
{
    __shared__ float As[128][GBK + 4];
    __shared__ float Bs[128][GBK + 4];
    int row0 = blockIdx.x * 128;
    int col0 = blockIdx.y * 128;
    int tid = threadIdx.x;
    int wid = tid >> 5;
    int lane = tid & 31;
    int g = lane >> 2, tg = lane & 3;
    int wm = (wid & 1) * 64;          // 2 warp-rows of 64
    int wn = (wid >> 1) * 32;         // 4 warp-cols of 32

    int m_base = tid >> 3;            // 0..31, row within 32-row chunk
    int kq = (tid & 7) * 4;           // k quad offset

    float c[4][4][4];
    #pragma unroll
    for (int i = 0; i < 4; i++)
        #pragma unroll
        for (int j = 0; j < 4; j++)
            #pragma unroll
            for (int l = 0; l < 4; l++) c[i][j][l] = 0.f;

    float4 pa[4], pb[4];
    #pragma unroll
    for (int it = 0; it < 4; it++) {
        pa[it] = *(const float4*)&A[(size_t)(row0 + m_base + it * 32) * K + kq];
        pb[it] = *(const float4*)&W[(size_t)(col0 + m_base + it * 32) * K + kq];
    }

    for (int kb = 0; kb < K; kb += GBK) {
        // store prefetched tile to smem (tf32-rounded)
        #pragma unroll
        for (int it = 0; it < 4; it++) {
            float4 v = pa[it];
            v.x = to_tf32(v.x); v.y = to_tf32(v.y); v.z = to_tf32(v.z); v.w = to_tf32(v.w);
            *(float4*)&As[m_base + it * 32][kq] = v;
            float4 w = pb[it];
            w.x = to_tf32(w.x); w.y = to_tf32(w.y); w.z = to_tf32(w.z); w.w = to_tf32(w.w);
            *(float4*)&Bs[m_base + it * 32][kq] = w;
        }
        __syncthreads();
        // prefetch next tile
        if (kb + GBK < K) {
            #pragma unroll
            for (int it = 0; it < 4; it++) {
                pa[it] = *(const float4*)&A[(size_t)(row0 + m_base + it * 32) * K + kb + GBK + kq];
                pb[it] = *(const float4*)&W[(size_t)(col0 + m_base + it * 32) * K + kb + GBK + kq];
            }
        }
        // MMA: 4 k-slices of 8
        #pragma unroll
        for (int ks = 0; ks < 4; ks++) {
            int k0 = ks * 8;
            uint32_t b[4][2];
            #pragma unroll
            for (int nt = 0; nt < 4; nt++) {
                int n = wn + nt * 8 + g;
                b[nt][0] = __float_as_uint(Bs[n][k0 + tg]);
                b[nt][1] = __float_as_uint(Bs[n][k0 + tg + 4]);
            }
            #pragma unroll
            for (int mt = 0; mt < 4; mt++) {
                int m = wm + mt * 16 + g;
                uint32_t a0 = __float_as_uint(As[m][k0 + tg]);
                uint32_t a1 = __float_as_uint(As[m + 8][k0 + tg]);
                uint32_t a2 = __float_as_uint(As[m][k0 + tg + 4]);
                uint32_t a3 = __float_as_uint(As[m + 8][k0 + tg + 4]);
                #pragma unroll
                for (int nt = 0; nt < 4; nt++) {
                    asm volatile(
                        "mma.sync.aligned.m16n8k8.row.col.f32.tf32.tf32.f32 "
                        "{%0,%1,%2,%3}, {%4,%5,%6,%7}, {%8,%9}, {%0,%1,%2,%3};"
                        : "+f"(c[mt][nt][0]), "+f"(c[mt][nt][1]),
                          "+f"(c[mt][nt][2]), "+f"(c[mt][nt][3])
                        : "r"(a0), "r"(a1), "r"(a2), "r"(a3),
                          "r"(b[nt][0]), "r"(b[nt][1]));
                }
            }
        }
        __syncthreads();
    }

    // epilogue (+optional fused column stats)
    float s0[4] = {0.f, 0.f, 0.f, 0.f}, s1[4] = {0.f, 0.f, 0.f, 0.f};
    float q0[4] = {0.f, 0.f, 0.f, 0.f}, q1[4] = {0.f, 0.f, 0.f, 0.f};
    #pragma unroll
    for (int mt = 0; mt < 4; mt++) {
        #pragma unroll
        for (int nt = 0; nt < 4; nt++) {
            int r = row0 + wm + mt * 16 + g;
            int cc = col0 + wn + nt * 8 + 2 * tg;
            float2 bv = *(const float2*)&bias[cc];
            float v0 = c[mt][nt][0] + bv.x;
            float v1 = c[mt][nt][1] + bv.y;
            float v2 = c[mt][nt][2] + bv.x;
            float v3 = c[mt][nt][3] + bv.y;
            if (resid) {
                float2 r0v = *(const float2*)&resid[(size_t)r * NC + cc];
                float2 r1v = *(const float2*)&resid[(size_t)(r + 8) * NC + cc];
                v0 += r0v.x; v1 += r0v.y; v2 += r1v.x; v3 += r1v.y;
            }
            if (relu) {
                v0 = fmaxf(v0, 0.f); v1 = fmaxf(v1, 0.f);
                v2 = fmaxf(v2, 0.f); v3 = fmaxf(v3, 0.f);
            }
            *(float2*)&out[(size_t)r * NC + cc] = make_float2(v0, v1);
            *(float2*)&out[(size_t)(r + 8) * NC + cc] = make_float2(v2, v3);
            if (ssum) {
                s0[nt] += v0 + v2;
                s1[nt] += v1 + v3;
                q0[nt] += v0 * v0 + v2 * v2;
                q1[nt] += v1 * v1 + v3 * v3;
            }
        }
    }
    if (ssum) {
        #pragma unroll
        for (int nt = 0; nt < 4; nt++) {
            #pragma unroll
            for (int off = 4; off <= 16; off <<= 1) {
                s0[nt] += __shfl_xor_sync(0xffffffffu, s0[nt], off);
                s1[nt] += __shfl_xor_sync(0xffffffffu, s1[nt], off);
                q0[nt] += __shfl_xor_sync(0xffffffffu, q0[nt], off);
                q1[nt] += __shfl_xor_sync(0xffffffffu, q1[nt], off);
            }
            if (lane < 4) {
                int cc = col0 + wn + nt * 8 + 2 * tg;
                atomicAdd(&ssum[cc], s0[nt]);
                atomicAdd(&ssq[cc],  q0[nt]);
                atomicAdd(&ssum[cc + 1], s1[nt]);
                atomicAdd(&ssq[cc + 1],  q1[nt]);
            }
        }
    }
}

// ---------------- tensor-core flash attention (validated R5) ----------------
#define KT 64
#define KS_PAD 36
#define VS_PAD 40
#define PS_PAD 68
#define ATTN_SMEM ((KT * KS_PAD + KT * VS_PAD + 8 * 16 * PS_PAD) * 4)
__global__ void __launch_bounds__(256) k_attn_tc(const float* __restrict__ qkv,
                                                 float* __restrict__ ao)
{
    extern __shared__ float sm[];
    float* Ks = sm;
    float* Vs = Ks + KT * KS_PAD;
    int tid = threadIdx.x;
    int wid = tid >> 5;
    int lane = tid & 31;
    int g = lane >> 2, tg = lane & 3;
    float* Ps = Vs + KT * VS_PAD + wid * 16 * PS_PAD;

    int blk = blockIdx.x;
    int qt = blk & 3;
    int bh = blk >> 2;
    int b = bh >> 2;
    int h = bh & 3;
    const float* base = qkv + (size_t)b * NNODE * (3 * CCH);
    int qrow0 = qt * 128 + wid * 16;
    const float SCALE = 0.1767766952966369f;

    uint32_t qa[4][4];
    #pragma unroll
    for (int kc = 0; kc < 4; kc++) {
        const float* q0 = base + (size_t)(qrow0 + g) * (3 * CCH) + h * DHEAD + 8 * kc;
        const float* q1 = base + (size_t)(qrow0 + g + 8) * (3 * CCH) + h * DHEAD + 8 * kc;
        qa[kc][0] = __float_as_uint(to_tf32(q0[tg]));
        qa[kc][1] = __float_as_uint(to_tf32(q1[tg]));
        qa[kc][2] = __float_as_uint(to_tf32(q0[tg + 4]));
        qa[kc][3] = __float_as_uint(to_tf32(q1[tg + 4]));
    }

    float m0 = -1e30f, m1 = -1e30f, l0 = 0.f, l1 = 0.f;
    float o[4][4];
    #pragma unroll
    for (int i = 0; i < 4; i++)
        #pragma unroll
        for (int j = 0; j < 4; j++) o[i][j] = 0.f;

    for (int kt = 0; kt < NNODE / KT; kt++) {
        #pragma unroll
        for (int it = 0; it < 2; it++) {
            int idx = tid + it * 256;
            int row = idx >> 3;
            int c4 = (idx & 7) * 4;
            const float* krow = base + (size_t)(kt * KT + row) * (3 * CCH) + CCH + h * DHEAD;
            const float* vrow = base + (size_t)(kt * KT + row) * (3 * CCH) + 2 * CCH + h * DHEAD;
            float4 kv = *(const float4*)(krow + c4);
            float4 vv = *(const float4*)(vrow + c4);
            kv.x = to_tf32(kv.x); kv.y = to_tf32(kv.y); kv.z = to_tf32(kv.z); kv.w = to_tf32(kv.w);
            vv.x = to_tf32(vv.x); vv.y = to_tf32(vv.y); vv.z = to_tf32(vv.z); vv.w = to_tf32(vv.w);
            *(float4*)(Ks + row * KS_PAD + c4) = kv;
            *(float4*)(Vs + row * VS_PAD + c4) = vv;
        }
        __syncthreads();

        float s[8][4];
        #pragma unroll
        for (int nt = 0; nt < 8; nt++)
            #pragma unroll
            for (int j = 0; j < 4; j++) s[nt][j] = 0.f;
        #pragma unroll
        for (int kc = 0; kc < 4; kc++) {
            #pragma unroll
            for (int nt = 0; nt < 8; nt++) {
                uint32_t b0 = __float_as_uint(Ks[(nt * 8 + g) * KS_PAD + 8 * kc + tg]);
                uint32_t b1 = __float_as_uint(Ks[(nt * 8 + g) * KS_PAD + 8 * kc + tg + 4]);
                asm volatile(
                    "mma.sync.aligned.m16n8k8.row.col.f32.tf32.tf32.f32 "
                    "{%0,%1,%2,%3}, {%4,%5,%6,%7}, {%8,%9}, {%0,%1,%2,%3};"
                    : "+f"(s[nt][0]), "+f"(s[nt][1]), "+f"(s[nt][2]), "+f"(s[nt][3])
                    : "r"(qa[kc][0]), "r"(qa[kc][1]), "r"(qa[kc][2]), "r"(qa[kc][3]),
                      "r"(b0), "r"(b1));
            }
        }
        float mx0 = -1e30f, mx1 = -1e30f;
        #pragma unroll
        for (int nt = 0; nt < 8; nt++) {
            s[nt][0] *= SCALE; s[nt][1] *= SCALE; s[nt][2] *= SCALE; s[nt][3] *= SCALE;
            mx0 = fmaxf(mx0, fmaxf(s[nt][0], s[nt][1]));
            mx1 = fmaxf(mx1, fmaxf(s[nt][2], s[nt][3]));
        }
        #pragma unroll
        for (int off = 1; off <= 2; off <<= 1) {
            mx0 = fmaxf(mx0, __shfl_xor_sync(0xffffffffu, mx0, off));
            mx1 = fmaxf(mx1, __shfl_xor_sync(0xffffffffu, mx1, off));
        }
        float nm0 = fmaxf(m0, mx0), nm1 = fmaxf(m1, mx1);
        float f0 = __expf(m0 - nm0), f1 = __expf(m1 - nm1);
        m0 = nm0; m1 = nm1;
        float rs0 = 0.f, rs1 = 0.f;
        #pragma unroll
        for (int nt = 0; nt < 8; nt++) {
            float p0 = __expf(s[nt][0] - m0);
            float p1 = __expf(s[nt][1] - m0);
            float p2 = __expf(s[nt][2] - m1);
            float p3 = __expf(s[nt][3] - m1);
            rs0 += p0 + p1; rs1 += p2 + p3;
            *(float2*)(Ps + g * PS_PAD + nt * 8 + 2 * tg)       = make_float2(to_tf32(p0), to_tf32(p1));
            *(float2*)(Ps + (g + 8) * PS_PAD + nt * 8 + 2 * tg) = make_float2(to_tf32(p2), to_tf32(p3));
        }
        #pragma unroll
        for (int off = 1; off <= 2; off <<= 1) {
            rs0 += __shfl_xor_sync(0xffffffffu, rs0, off);
            rs1 += __shfl_xor_sync(0xffffffffu, rs1, off);
        }
        l0 = l0 * f0 + rs0;
        l1 = l1 * f1 + rs1;
        #pragma unroll
        for (int nt = 0; nt < 4; nt++) {
            o[nt][0] *= f0; o[nt][1] *= f0; o[nt][2] *= f1; o[nt][3] *= f1;
        }
        __syncwarp();
        #pragma unroll
        for (int kc = 0; kc < 8; kc++) {
            uint32_t a0 = __float_as_uint(Ps[g * PS_PAD + 8 * kc + tg]);
            uint32_t a1 = __float_as_uint(Ps[(g + 8) * PS_PAD + 8 * kc + tg]);
            uint32_t a2 = __float_as_uint(Ps[g * PS_PAD + 8 * kc + tg + 4]);
            uint32_t a3 = __float_as_uint(Ps[(g + 8) * PS_PAD + 8 * kc + tg + 4]);
            #pragma unroll
            for (int nt = 0; nt < 4; nt++) {
                uint32_t b0 = __float_as_uint(Vs[(8 * kc + tg) * VS_PAD + 8 * nt + g]);
                uint32_t b1 = __float_as_uint(Vs[(8 * kc + tg + 4) * VS_PAD + 8 * nt + g]);
                asm volatile(
                    "mma.sync.aligned.m16n8k8.row.col.f32.tf32.tf32.f32 "
                    "{%0,%1,%2,%3}, {%4,%5,%6,%7}, {%8,%9}, {%0,%1,%2,%3};"
                    : "+f"(o[nt][0]), "+f"(o[nt][1]), "+f"(o[nt][2]), "+f"(o[nt][3])
                    : "r"(a0), "r"(a1), "r"(a2), "r"(a3), "r"(b0), "r"(b1));
            }
        }
        __syncthreads();
    }

    float inv0 = 1.f / l0, inv1 = 1.f / l1;
    #pragma unroll
    for (int nt = 0; nt < 4; nt++) {
        int cc = h * DHEAD + nt * 8 + 2 * tg;
        int r0 = b * NNODE + qrow0 + g;
        *(float2*)&ao[(size_t)r0 * CCH + cc] = make_float2(o[nt][0] * inv0, o[nt][1] * inv0);
        *(float2*)&ao[(size_t)(r0 + 8) * CCH + cc] = make_float2(o[nt][2] * inv1, o[nt][3] * inv1);
    }
}

// ---------------- combine: out1 = BN1(h1) + BN2(h2) ----------------
__global__ void k_combine(const float* __restrict__ h1, const float* __restrict__ h2,
                          const float* __restrict__ g1, const float* __restrict__ b1,
                          const float* __restrict__ g2, const float* __restrict__ b2,
                          float* __restrict__ out1)
{
    int i = blockIdx.x * blockDim.x + threadIdx.x;
    if (i >= NTN * CCH / 4) return;
    int c0 = (i & 31) * 4;
    float4 a = ((const float4*)h1)[i];
    float4 bb = ((const float4*)h2)[i];
    float av[4] = { a.x, a.y, a.z, a.w };
    float bv[4] = { bb.x, bb.y, bb.z, bb.w };
    float rv[4];
    const float invn = 1.f / (float)NTN;
    #pragma unroll
    for (int j = 0; j < 4; j++) {
        int c = c0 + j;
        float m1 = d_stats[c] * invn;
        float v1 = d_stats[CCH + c] * invn - m1 * m1;
        float k1 = rsqrtf(v1 + EPSBN) * g1[c];
        float m2 = d_stats[2 * CCH + c] * invn;
        float v2 = d_stats[3 * CCH + c] * invn - m2 * m2;
        float k2 = rsqrtf(v2 + EPSBN) * g2[c];
        rv[j] = (av[j] - m1) * k1 + b1[c] + (bv[j] - m2) * k2 + b2[c];
    }
    ((float4*)out1)[i] = make_float4(rv[0], rv[1], rv[2], rv[3]);
}

// ---------------- final: out = BN3(out2) ----------------
__global__ void k_final(const float* __restrict__ src,
                        const float* __restrict__ g3, const float* __restrict__ b3,
                        float* __restrict__ out)
{
    int i = blockIdx.x * blockDim.x + threadIdx.x;
    if (i >= NTN * CCH / 4) return;
    int c0 = (i & 31) * 4;
    float4 a = ((const float4*)src)[i];
    float av[4] = { a.x, a.y, a.z, a.w };
    float rv[4];
    const float invn = 1.f / (float)NTN;
    #pragma unroll
    for (int j = 0; j < 4; j++) {
        int c = c0 + j;
        float m = d_stats[4 * CCH + c] * invn;
        float v = d_stats[5 * CCH + c] * invn - m * m;
        float k = rsqrtf(v + EPSBN) * g3[c];
        rv[j] = (av[j] - m) * k + b3[c];
    }
    ((float4*)out)[i] = make_float4(rv[0], rv[1], rv[2], rv[3]);
}

// ---------------- host launcher ----------------
extern "C" void kernel_launch(void* const* d_in, const int* in_sizes, int n_in,
                              void* d_out, int out_size)
{
    const float* x    = (const float*)d_in[0];
    const int*   ei   = (const int*)d_in[1];
    const float* Wc   = (const float*)d_in[2];
    const float* bc   = (const float*)d_in[3];
    const float* Winp = (const float*)d_in[4];
    const float* binp = (const float*)d_in[5];
    const float* Wout = (const float*)d_in[6];
    const float* bout = (const float*)d_in[7];
    const float* gn1  = (const float*)d_in[8];
    const float* bn1  = (const float*)d_in[9];
    const float* gn2  = (const float*)d_in[10];
    const float* bn2  = (const float*)d_in[11];
    const float* gn3  = (const float*)d_in[12];
    const float* bn3  = (const float*)d_in[13];
    const float* Wm1  = (const float*)d_in[14];
    const float* bm1  = (const float*)d_in[15];
    const float* Wm2  = (const float*)d_in[16];
    const float* bm2  = (const float*)d_in[17];
    float* out = (float*)d_out;

    float *agg, *h1, *qkv, *ao, *h2, *out1, *hid, *out2, *stats;
    cudaGetSymbolAddress((void**)&agg,  d_agg);
    cudaGetSymbolAddress((void**)&h1,   d_h1);
    cudaGetSymbolAddress((void**)&qkv,  d_qkv);
    cudaGetSymbolAddress((void**)&ao,   d_ao);
    cudaGetSymbolAddress((void**)&h2,   d_h2);
    cudaGetSymbolAddress((void**)&out1, d_out1);
    cudaGetSymbolAddress((void**)&hid,  d_hid);
    cudaGetSymbolAddress((void**)&out2, d_out2);
    cudaGetSymbolAddress((void**)&stats, d_stats);

    cudaFuncSetAttribute(k_attn_tc, cudaFuncAttributeMaxDynamicSharedMemorySize, ATTN_SMEM);

    // --- edge CSR + mean aggregation ---
    k_init<<<NTN / 256, 256>>>();
    k_count<<<NEDGE / 256, 256>>>(ei);
    k_scan<<<1, 1024>>>();
    k_bin<<<NEDGE / 256, 256>>>(ei);
    k_agg<<<NTN * 32 / 256, 256>>>(x);

    // --- local branch: h1 = agg @ Wc^T + bc + x ; fused stats1 ---
    k_gemm2<<<dim3(NTN / 128, 1), 256>>>(agg, Wc, bc, x, h1, stats, stats + CCH,
                                         NTN, 128, 128, 0);

    // --- global branch ---
    k_gemm2<<<dim3(NTN / 128, 3), 256>>>(x, Winp, binp, nullptr, qkv, nullptr, nullptr,
                                         NTN, 384, 128, 0);
    k_attn_tc<<<BATCH * NH * 4, 256, ATTN_SMEM>>>(qkv, ao);
    k_gemm2<<<dim3(NTN / 128, 1), 256>>>(ao, Wout, bout, x, h2, stats + 2 * CCH, stats + 3 * CCH,
                                         NTN, 128, 128, 0);

    // --- combine + MLP + final BN ---
    k_combine<<<NTN * CCH / 4 / 256, 256>>>(h1, h2, gn1, bn1, gn2, bn2, out1);
    k_gemm2<<<dim3(NTN / 128, 2), 256>>>(out1, Wm1, bm1, nullptr, hid, nullptr, nullptr,
                                         NTN, 256, 128, 1);
    k_gemm2<<<dim3(NTN / 128, 1), 256>>>(hid, Wm2, bm2, out1, out2, stats + 4 * CCH, stats + 5 * CCH,
                                         NTN, 128, 256, 0);
    k_final<<<NTN * CCH / 4 / 256, 256>>>(out2, gn3, bn3, out);
}